// round 9
// baseline (speedup 1.0000x reference)
#include <cuda_runtime.h>
#include <cuda_bf16.h>
#include <cstdint>

// ============================================================
// RankingLoss: bf16 mma.sync with 64x64 warp tiles + fused hinge.
// loss = sum_{b,c: tc[c]!=label[b]} max(1 + pred_b·sigc_c - gt_b, 0)
// ============================================================

#define MAX_B   16384
#define DDIM    256
#define CPAD    2048
#define MAX_PART 4096

__device__ float g_gt[MAX_B];
__device__ float g_partial[MAX_PART];
__device__ __nv_bfloat16 g_predb[MAX_B * DDIM];   // pred bf16 [b][d]
__device__ __nv_bfloat16 g_sgath[CPAD * DDIM];    // gathered sig bf16 [c][d]
__device__ float g_sigT[CPAD * DDIM];             // sig transposed fp32 [c][d]
__device__ int g_tcs[CPAD];                        // class ids (-1 pad)

// ---------------- transpose sig fp32: [d][c] -> [c][d] ----------------
__global__ void transpose_sig_kernel(const float* __restrict__ sig, int C) {
    __shared__ float t[32][33];
    int cb = blockIdx.x * 32, db = blockIdx.y * 32;
    int tx = threadIdx.x & 31, ty = threadIdx.x >> 5;  // 256 thr
    #pragma unroll
    for (int i = 0; i < 32; i += 8) {
        int d = db + ty + i, c = cb + tx;
        t[ty + i][tx] = (c < C) ? sig[(size_t)d * C + c] : 0.f;
    }
    __syncthreads();
    #pragma unroll
    for (int i = 0; i < 32; i += 8) {
        int c = cb + ty + i, d = db + tx;
        if (c < CPAD) g_sigT[(size_t)c * DDIM + d] = t[tx][ty + i];
    }
}

// ---------------- prep: pred -> bf16 ----------------
__global__ void prep_pred_kernel(const float* __restrict__ pred, int n8) {
    int i = blockIdx.x * blockDim.x + threadIdx.x;
    if (i >= n8) return;
    const float4* s = (const float4*)pred + i * 2;
    float4 a = s[0], b = s[1];
    __nv_bfloat162 o[4];
    o[0] = __nv_bfloat162(__float2bfloat16(a.x), __float2bfloat16(a.y));
    o[1] = __nv_bfloat162(__float2bfloat16(a.z), __float2bfloat16(a.w));
    o[2] = __nv_bfloat162(__float2bfloat16(b.x), __float2bfloat16(b.y));
    o[3] = __nv_bfloat162(__float2bfloat16(b.z), __float2bfloat16(b.w));
    *(uint4*)&g_predb[(size_t)i * 8] = *(uint4*)o;
}

// ---------------- prep: gathered sig -> bf16 (coalesced via sigT) ----------------
__global__ void prep_sig_kernel(const int* __restrict__ tclass, int C) {
    int t = blockIdx.x * blockDim.x + threadIdx.x;   // CPAD*32 threads
    int c = t >> 5;
    int d0 = (t & 31) << 3;
    if (c >= CPAD) return;
    __nv_bfloat162 o[4];
    if (c < C) {
        int cls = tclass[c];
        const float4* s4 = (const float4*)&g_sigT[(size_t)cls * DDIM + d0];
        float4 a = s4[0], b = s4[1];
        o[0] = __nv_bfloat162(__float2bfloat16(a.x), __float2bfloat16(a.y));
        o[1] = __nv_bfloat162(__float2bfloat16(a.z), __float2bfloat16(a.w));
        o[2] = __nv_bfloat162(__float2bfloat16(b.x), __float2bfloat16(b.y));
        o[3] = __nv_bfloat162(__float2bfloat16(b.z), __float2bfloat16(b.w));
        if ((t & 31) == 0) g_tcs[c] = cls;
    } else {
        #pragma unroll
        for (int i = 0; i < 4; i++) o[i] = __nv_bfloat162(__float2bfloat16(0.f), __float2bfloat16(0.f));
        if ((t & 31) == 0) g_tcs[c] = -1;
    }
    *(uint4*)&g_sgath[(size_t)c * DDIM + d0] = *(uint4*)o;
}

// ---------------- gt: exact fp32, coalesced via sigT ----------------
__global__ void gt_kernel(const float* __restrict__ pred,
                          const int* __restrict__ label, int B) {
    int b = blockIdx.x * (blockDim.x >> 5) + (threadIdx.x >> 5);
    if (b >= B) return;
    int lane = threadIdx.x & 31;
    int lb = label[b];
    const float4* p4 = (const float4*)pred + (size_t)b * 64;
    const float4* s4 = (const float4*)g_sigT + (size_t)lb * 64;
    float4 a0 = p4[lane], a1 = p4[lane + 32];
    float4 c0 = s4[lane], c1 = s4[lane + 32];
    float s = a0.x*c0.x + a0.y*c0.y + a0.z*c0.z + a0.w*c0.w
            + a1.x*c1.x + a1.y*c1.y + a1.z*c1.z + a1.w*c1.w;
    #pragma unroll
    for (int o = 16; o > 0; o >>= 1) s += __shfl_down_sync(0xffffffffu, s, o);
    if (lane == 0) g_gt[b] = s;
}

// ---------------- fused MMA GEMM + hinge ----------------
// CTA tile 128 rows x 256 classes, 256 threads (8 warps 2m x 4n, warp 64x64).
#define A_OFF    0
#define B_OFF    65536
#define TCS_OFF  196608
#define GT_OFF   197632
#define LB_OFF   198144
#define RED_OFF  198656
#define SMEM_TOTAL 199680

__device__ __forceinline__ uint32_t smem_u32(const void* p) {
    uint32_t a;
    asm("{ .reg .u64 t; cvta.to.shared.u64 t, %1; cvt.u32.u64 %0, t; }" : "=r"(a) : "l"(p));
    return a;
}

#define CP_ASYNC16(dst, src) \
    asm volatile("cp.async.cg.shared.global [%0], [%1], 16;" :: "r"(dst), "l"(src) : "memory")
#define CP_COMMIT() asm volatile("cp.async.commit_group;" ::: "memory")
#define CP_WAIT(n)  asm volatile("cp.async.wait_group %0;" :: "n"(n) : "memory")

#define LDMX4(r0, r1, r2, r3, a) \
    asm volatile("ldmatrix.sync.aligned.m8n8.x4.shared.b16 {%0,%1,%2,%3}, [%4];" \
        : "=r"(r0), "=r"(r1), "=r"(r2), "=r"(r3) : "r"(a))

#define MMA16816(c, A, b0, b1) \
    asm volatile("mma.sync.aligned.m16n8k16.row.col.f32.bf16.bf16.f32 " \
        "{%0,%1,%2,%3}, {%4,%5,%6,%7}, {%8,%9}, {%0,%1,%2,%3};" \
        : "+f"((c)[0]), "+f"((c)[1]), "+f"((c)[2]), "+f"((c)[3]) \
        : "r"((A)[0]), "r"((A)[1]), "r"((A)[2]), "r"((A)[3]), "r"(b0), "r"(b1))

__device__ __forceinline__ void do_kstep(int ks, float (&acc)[4][8][4],
                                         const uint32_t (&baseA)[4],
                                         const uint32_t (&baseB)[4],
                                         uint32_t u0, uint32_t xr) {
    const uint32_t t = (((uint32_t)(2 * ks) + u0) ^ xr) << 4;
    uint32_t a[4][4];
    #pragma unroll
    for (int mi = 0; mi < 4; mi++)
        LDMX4(a[mi][0], a[mi][1], a[mi][2], a[mi][3], baseA[mi] + t);
    uint32_t b[8][2];
    #pragma unroll
    for (int p = 0; p < 4; p++) {
        uint32_t q0, q1, q2, q3;
        LDMX4(q0, q1, q2, q3, baseB[p] + t);
        b[2*p][0] = q0;   b[2*p][1] = q2;
        b[2*p+1][0] = q1; b[2*p+1][1] = q3;
    }
    #pragma unroll
    for (int mi = 0; mi < 4; mi++)
        #pragma unroll
        for (int ni = 0; ni < 8; ni++)
            MMA16816(acc[mi][ni], a[mi], b[ni][0], b[ni][1]);
}

__global__ __launch_bounds__(256, 1)
void hinge_mma_kernel(const int* __restrict__ label) {
    extern __shared__ char smem[];
    const uint32_t sb = smem_u32(smem);
    const int tid = threadIdx.x, lane = tid & 31, wid = tid >> 5;
    const int c0 = blockIdx.x * 256;       // class-tile base
    const int r0 = blockIdx.y * 128;       // row-tile base

    // ---- cp.async fills: one commit group per 64-k chunk ----
    #pragma unroll
    for (int ch = 0; ch < 4; ch++) {
        #pragma unroll
        for (int i = 0; i < 4; i++) {          // A: 128 rows x 8 units
            int q = tid + i * 256;
            int row = q >> 3, u = ch * 8 + (q & 7);
            uint32_t dst = sb + A_OFF + (uint32_t)row * 512u + (uint32_t)((u ^ (row & 7)) << 4);
            size_t src = __cvta_generic_to_global(&g_predb[(size_t)(r0 + row) * DDIM + u * 8]);
            CP_ASYNC16(dst, src);
        }
        #pragma unroll
        for (int i = 0; i < 8; i++) {          // B: 256 rows x 8 units
            int q = tid + i * 256;
            int row = q >> 3, u = ch * 8 + (q & 7);
            uint32_t dst = sb + B_OFF + (uint32_t)row * 512u + (uint32_t)((u ^ (row & 7)) << 4);
            size_t src = __cvta_generic_to_global(&g_sgath[(size_t)(c0 + row) * DDIM + u * 8]);
            CP_ASYNC16(dst, src);
        }
        CP_COMMIT();
    }

    // metadata while fills fly
    ((int*)(smem + TCS_OFF))[tid] = g_tcs[c0 + tid];
    if (tid < 128) {
        ((float*)(smem + GT_OFF))[tid] = g_gt[r0 + tid];
        ((int*)(smem + LB_OFF))[tid]   = label[r0 + tid];
    }

    // Warp layout: 2 (m) x 4 (n); warp tile 64 x 64
    const int wm = (wid & 1) * 64;
    const int wn = (wid >> 1) * 64;

    float acc[4][8][4];
    #pragma unroll
    for (int mi = 0; mi < 4; mi++)
        #pragma unroll
        for (int ni = 0; ni < 8; ni++)
            #pragma unroll
            for (int q = 0; q < 4; q++) acc[mi][ni][q] = 0.f;

    const int lrow = lane & 15;
    const uint32_t u0 = (uint32_t)(lane >> 4);
    const uint32_t xr = (uint32_t)(lane & 7);
    uint32_t baseA[4], baseB[4];
    #pragma unroll
    for (int mi = 0; mi < 4; mi++)
        baseA[mi] = sb + A_OFF + (uint32_t)(wm + mi * 16 + lrow) * 512u;
    #pragma unroll
    for (int p = 0; p < 4; p++)
        baseB[p] = sb + B_OFF + (uint32_t)(wn + p * 16 + lrow) * 512u;

    // ---- pipelined k phases ----
    CP_WAIT(3); __syncthreads();
    #pragma unroll
    for (int ks = 0; ks < 4; ks++) do_kstep(ks, acc, baseA, baseB, u0, xr);
    CP_WAIT(2); __syncthreads();
    #pragma unroll
    for (int ks = 4; ks < 8; ks++) do_kstep(ks, acc, baseA, baseB, u0, xr);
    CP_WAIT(1); __syncthreads();
    #pragma unroll
    for (int ks = 8; ks < 12; ks++) do_kstep(ks, acc, baseA, baseB, u0, xr);
    CP_WAIT(0); __syncthreads();
    #pragma unroll
    for (int ks = 12; ks < 16; ks++) do_kstep(ks, acc, baseA, baseB, u0, xr);

    // ---- fused hinge epilogue ----
    const int* tcs = (const int*)(smem + TCS_OFF);
    const float* gts = (const float*)(smem + GT_OFF);
    const int* lbs = (const int*)(smem + LB_OFF);
    float lsum = 0.f;
    #pragma unroll
    for (int mi = 0; mi < 4; mi++) {
        #pragma unroll
        for (int half = 0; half < 2; half++) {
            const int r = wm + mi * 16 + (lane >> 2) + half * 8;
            const float base = 1.0f - gts[r];
            const int lb = lbs[r];
            #pragma unroll
            for (int ni = 0; ni < 8; ni++) {
                const int cbase = wn + ni * 8 + (lane & 3) * 2;
                #pragma unroll
                for (int e = 0; e < 2; e++) {
                    const int cls = tcs[cbase + e];
                    if (cls >= 0 && cls != lb)
                        lsum += fmaxf(acc[mi][ni][half * 2 + e] + base, 0.f);
                }
            }
        }
    }

    float* red = (float*)(smem + RED_OFF);
    red[tid] = lsum;
    __syncthreads();
    #pragma unroll
    for (int s = 128; s > 0; s >>= 1) {
        if (tid < s) red[tid] += red[tid + s];
        __syncthreads();
    }
    if (tid == 0) g_partial[blockIdx.y * gridDim.x + blockIdx.x] = red[0];
}

// ---------------- deterministic final reduce ----------------
__global__ void final_reduce_kernel(float* __restrict__ out, int n) {
    __shared__ float red[256];
    int tid = threadIdx.x;
    float s = 0.f;
    for (int i = tid; i < n; i += 256) s += g_partial[i];
    red[tid] = s;
    __syncthreads();
    #pragma unroll
    for (int o = 128; o > 0; o >>= 1) {
        if (tid < o) red[tid] += red[tid + o];
        __syncthreads();
    }
    if (tid == 0) out[0] = red[0];
}

extern "C" void kernel_launch(void* const* d_in, const int* in_sizes, int n_in,
                              void* d_out, int out_size) {
    const float* pred   = (const float*)d_in[0];
    const int*   label  = (const int*)d_in[1];
    const int*   tclass = (const int*)d_in[2];
    const float* sig    = (const float*)d_in[3];
    float* out = (float*)d_out;

    const int B = in_sizes[1];
    const int C = in_sizes[2];

    // transpose first; gather + gt read from sigT (coalesced)
    {
        dim3 tg((C + 31) / 32, DDIM / 32);
        transpose_sig_kernel<<<tg, 256>>>(sig, C);
    }
    prep_sig_kernel<<<(CPAD * 32) / 256, 256>>>(tclass, C);
    {
        int n8 = B * DDIM / 8;
        prep_pred_kernel<<<(n8 + 255) / 256, 256>>>(pred, n8);
    }
    gt_kernel<<<(B + 7) / 8, 256>>>(pred, label, B);

    // fused MMA GEMM + hinge
    cudaFuncSetAttribute(hinge_mma_kernel, cudaFuncAttributeMaxDynamicSharedMemorySize, SMEM_TOTAL);
    dim3 grid(CPAD / 256, B / 128);
    hinge_mma_kernel<<<grid, 256, SMEM_TOTAL>>>(label);

    // final reduce
    final_reduce_kernel<<<1, 256>>>(out, grid.x * grid.y);
}

// round 10
// speedup vs baseline: 1.2057x; 1.2057x over previous
#include <cuda_runtime.h>
#include <cuda_bf16.h>
#include <cstdint>

// ============================================================
// RankingLoss: persistent-CTA bf16 mma.sync GEMM with 4-slot
// cp.async k-chunk ring + fused hinge epilogue.
// loss = sum_{b,c: tc[c]!=label[b]} max(1 + pred_b·sigc_c - gt_b, 0)
// ============================================================

#define MAX_B   16384
#define DDIM    256
#define CPAD    2048
#define MAX_PART 4096
#define NTILE   ((CPAD / 256) * (MAX_B / 128))   // 1024
#define PGRID   148

__device__ float g_gt[MAX_B];
__device__ float g_partial[MAX_PART];
__device__ __nv_bfloat16 g_predb[MAX_B * DDIM];   // pred bf16 [b][d]
__device__ __nv_bfloat16 g_sgath[CPAD * DDIM];    // gathered sig bf16 [c][d]
__device__ float g_sigT[CPAD * DDIM];             // sig transposed fp32 [c][d]
__device__ int g_tcs[CPAD];                        // class ids (-1 pad)

// ---------------- transpose sig fp32: [d][c] -> [c][d] ----------------
__global__ void transpose_sig_kernel(const float* __restrict__ sig, int C) {
    __shared__ float t[32][33];
    int cb = blockIdx.x * 32, db = blockIdx.y * 32;
    int tx = threadIdx.x & 31, ty = threadIdx.x >> 5;
    #pragma unroll
    for (int i = 0; i < 32; i += 8) {
        int d = db + ty + i, c = cb + tx;
        t[ty + i][tx] = (c < C) ? sig[(size_t)d * C + c] : 0.f;
    }
    __syncthreads();
    #pragma unroll
    for (int i = 0; i < 32; i += 8) {
        int c = cb + ty + i, d = db + tx;
        if (c < CPAD) g_sigT[(size_t)c * DDIM + d] = t[tx][ty + i];
    }
}

// ---------------- prep: pred -> bf16 ----------------
__global__ void prep_pred_kernel(const float* __restrict__ pred, int n8) {
    int i = blockIdx.x * blockDim.x + threadIdx.x;
    if (i >= n8) return;
    const float4* s = (const float4*)pred + i * 2;
    float4 a = s[0], b = s[1];
    __nv_bfloat162 o[4];
    o[0] = __nv_bfloat162(__float2bfloat16(a.x), __float2bfloat16(a.y));
    o[1] = __nv_bfloat162(__float2bfloat16(a.z), __float2bfloat16(a.w));
    o[2] = __nv_bfloat162(__float2bfloat16(b.x), __float2bfloat16(b.y));
    o[3] = __nv_bfloat162(__float2bfloat16(b.z), __float2bfloat16(b.w));
    *(uint4*)&g_predb[(size_t)i * 8] = *(uint4*)o;
}

// ---------------- prep: gathered sig -> bf16 (coalesced via sigT) ----------------
__global__ void prep_sig_kernel(const int* __restrict__ tclass, int C) {
    int t = blockIdx.x * blockDim.x + threadIdx.x;
    int c = t >> 5;
    int d0 = (t & 31) << 3;
    if (c >= CPAD) return;
    __nv_bfloat162 o[4];
    if (c < C) {
        int cls = tclass[c];
        const float4* s4 = (const float4*)&g_sigT[(size_t)cls * DDIM + d0];
        float4 a = s4[0], b = s4[1];
        o[0] = __nv_bfloat162(__float2bfloat16(a.x), __float2bfloat16(a.y));
        o[1] = __nv_bfloat162(__float2bfloat16(a.z), __float2bfloat16(a.w));
        o[2] = __nv_bfloat162(__float2bfloat16(b.x), __float2bfloat16(b.y));
        o[3] = __nv_bfloat162(__float2bfloat16(b.z), __float2bfloat16(b.w));
        if ((t & 31) == 0) g_tcs[c] = cls;
    } else {
        #pragma unroll
        for (int i = 0; i < 4; i++) o[i] = __nv_bfloat162(__float2bfloat16(0.f), __float2bfloat16(0.f));
        if ((t & 31) == 0) g_tcs[c] = -1;
    }
    *(uint4*)&g_sgath[(size_t)c * DDIM + d0] = *(uint4*)o;
}

// ---------------- gt: exact fp32, coalesced via sigT ----------------
__global__ void gt_kernel(const float* __restrict__ pred,
                          const int* __restrict__ label, int B) {
    int b = blockIdx.x * (blockDim.x >> 5) + (threadIdx.x >> 5);
    if (b >= B) return;
    int lane = threadIdx.x & 31;
    int lb = label[b];
    const float4* p4 = (const float4*)pred + (size_t)b * 64;
    const float4* s4 = (const float4*)g_sigT + (size_t)lb * 64;
    float4 a0 = p4[lane], a1 = p4[lane + 32];
    float4 c0 = s4[lane], c1 = s4[lane + 32];
    float s = a0.x*c0.x + a0.y*c0.y + a0.z*c0.z + a0.w*c0.w
            + a1.x*c1.x + a1.y*c1.y + a1.z*c1.z + a1.w*c1.w;
    #pragma unroll
    for (int o = 16; o > 0; o >>= 1) s += __shfl_down_sync(0xffffffffu, s, o);
    if (lane == 0) g_gt[b] = s;
}

// ---------------- persistent fused MMA GEMM + hinge ----------------
// Tile: 128 rows x 256 classes. 512 threads (16 warps, 4m x 4n, warp 32x64).
// Ring: 4 slots x (A 16KB + B 32KB) = 192KB; slot s: A @ s*48K, B @ s*48K+16K.
#define SLOT_SZ  49152
#define B_SUB    16384
#define RED_OFF  196608
#define SMEM_TOTAL 196736

__device__ __forceinline__ uint32_t smem_u32(const void* p) {
    uint32_t a;
    asm("{ .reg .u64 t; cvta.to.shared.u64 t, %1; cvt.u32.u64 %0, t; }" : "=r"(a) : "l"(p));
    return a;
}

#define CP_ASYNC16(dst, src) \
    asm volatile("cp.async.cg.shared.global [%0], [%1], 16;" :: "r"(dst), "l"(src) : "memory")
#define CP_COMMIT() asm volatile("cp.async.commit_group;" ::: "memory")
#define CP_WAIT2()  asm volatile("cp.async.wait_group 2;" ::: "memory")

#define LDMX4(r0, r1, r2, r3, a) \
    asm volatile("ldmatrix.sync.aligned.m8n8.x4.shared.b16 {%0,%1,%2,%3}, [%4];" \
        : "=r"(r0), "=r"(r1), "=r"(r2), "=r"(r3) : "r"(a))

#define MMA16816(c, A, b0, b1) \
    asm volatile("mma.sync.aligned.m16n8k16.row.col.f32.bf16.bf16.f32 " \
        "{%0,%1,%2,%3}, {%4,%5,%6,%7}, {%8,%9}, {%0,%1,%2,%3};" \
        : "+f"((c)[0]), "+f"((c)[1]), "+f"((c)[2]), "+f"((c)[3]) \
        : "r"((A)[0]), "r"((A)[1]), "r"((A)[2]), "r"((A)[3]), "r"(b0), "r"(b1))

// Fill one 64-k chunk of tile (ft) into ring slot fc. 512 threads.
__device__ __forceinline__ void fill_chunk(uint32_t sb, int ft, int fc, int tid) {
    const int r0f = (ft >> 3) * 128;
    const int c0f = (ft & 7) * 256;
    const uint32_t slot = sb + (uint32_t)fc * SLOT_SZ;
    #pragma unroll
    for (int i = 0; i < 2; i++) {              // A: 128 rows x 8 units
        int op = tid + i * 512;
        int row = op >> 3, u = op & 7;
        uint32_t dst = slot + (uint32_t)row * 128u + (uint32_t)((u ^ (row & 7)) << 4);
        size_t src = __cvta_generic_to_global(&g_predb[(size_t)(r0f + row) * DDIM + fc * 64 + u * 8]);
        CP_ASYNC16(dst, src);
    }
    #pragma unroll
    for (int i = 0; i < 4; i++) {              // B: 256 rows x 8 units
        int op = tid + i * 512;
        int row = op >> 3, u = op & 7;
        uint32_t dst = slot + B_SUB + (uint32_t)row * 128u + (uint32_t)((u ^ (row & 7)) << 4);
        size_t src = __cvta_generic_to_global(&g_sgath[(size_t)(c0f + row) * DDIM + fc * 64 + u * 8]);
        CP_ASYNC16(dst, src);
    }
}

__global__ __launch_bounds__(512, 1)
void hinge_mma_kernel(const int* __restrict__ label, int nt) {
    extern __shared__ char smem[];
    const uint32_t sb = smem_u32(smem);
    const int tid = threadIdx.x, lane = tid & 31, wid = tid >> 5;
    const int bid = blockIdx.x;

    const int wm = (wid & 3) * 32;             // warp 32 rows
    const int wn = (wid >> 2) * 64;            // warp 64 cols
    const int lrow = lane & 15;
    const uint32_t u0 = (uint32_t)(lane >> 4);
    const uint32_t xr = (uint32_t)(lane & 7);

    float acc[2][8][4];
    #pragma unroll
    for (int mi = 0; mi < 2; mi++)
        #pragma unroll
        for (int ni = 0; ni < 8; ni++)
            #pragma unroll
            for (int q = 0; q < 4; q++) acc[mi][ni][q] = 0.f;

    // ---- pipeline prologue: fill 3 chunks ahead ----
    int ft = bid, fc = 0;                      // next chunk to fill
    #pragma unroll
    for (int p = 0; p < 3; p++) {
        if (ft < nt) fill_chunk(sb, ft, fc, tid);
        CP_COMMIT();
        if (++fc == 4) { fc = 0; ft += PGRID; }
    }

    for (int tile = bid; tile < nt; tile += PGRID) {
        #pragma unroll
        for (int ch = 0; ch < 4; ch++) {
            CP_WAIT2();
            __syncthreads();
            // issue next fill (3 ahead) into the slot just freed
            if (ft < nt) fill_chunk(sb, ft, fc, tid);
            CP_COMMIT();
            if (++fc == 4) { fc = 0; ft += PGRID; }
            // ---- MMA on chunk ch (4 k-steps) ----
            const uint32_t slot = sb + (uint32_t)ch * SLOT_SZ;
            uint32_t baseA0 = slot + (uint32_t)(wm + lrow) * 128u;
            uint32_t baseA1 = slot + (uint32_t)(wm + 16 + lrow) * 128u;
            uint32_t baseB0 = slot + B_SUB + (uint32_t)(wn + lrow) * 128u;
            uint32_t baseB1 = baseB0 + 16u * 128u;
            uint32_t baseB2 = baseB0 + 32u * 128u;
            uint32_t baseB3 = baseB0 + 48u * 128u;
            #pragma unroll
            for (int kk = 0; kk < 4; kk++) {
                const uint32_t t = (((uint32_t)(2 * kk) + u0) ^ xr) << 4;
                uint32_t a[2][4];
                LDMX4(a[0][0], a[0][1], a[0][2], a[0][3], baseA0 + t);
                LDMX4(a[1][0], a[1][1], a[1][2], a[1][3], baseA1 + t);
                uint32_t b[8][2];
                {
                    uint32_t q0, q1, q2, q3;
                    LDMX4(q0, q1, q2, q3, baseB0 + t);
                    b[0][0] = q0; b[0][1] = q2; b[1][0] = q1; b[1][1] = q3;
                    LDMX4(q0, q1, q2, q3, baseB1 + t);
                    b[2][0] = q0; b[2][1] = q2; b[3][0] = q1; b[3][1] = q3;
                    LDMX4(q0, q1, q2, q3, baseB2 + t);
                    b[4][0] = q0; b[4][1] = q2; b[5][0] = q1; b[5][1] = q3;
                    LDMX4(q0, q1, q2, q3, baseB3 + t);
                    b[6][0] = q0; b[6][1] = q2; b[7][0] = q1; b[7][1] = q3;
                }
                #pragma unroll
                for (int mi = 0; mi < 2; mi++)
                    #pragma unroll
                    for (int ni = 0; ni < 8; ni++)
                        MMA16816(acc[mi][ni], a[mi], b[ni][0], b[ni][1]);
            }
        }

        // ---- fused hinge epilogue for this tile ----
        const int r0 = (tile >> 3) * 128;
        const int c0 = (tile & 7) * 256;
        float lsum = 0.f;
        #pragma unroll
        for (int mi = 0; mi < 2; mi++) {
            #pragma unroll
            for (int half = 0; half < 2; half++) {
                const int r = r0 + wm + mi * 16 + (lane >> 2) + half * 8;
                const float base = 1.0f - g_gt[r];
                const int lb = __ldg(&label[r]);
                #pragma unroll
                for (int ni = 0; ni < 8; ni++) {
                    const int cb = c0 + wn + ni * 8 + (lane & 3) * 2;
                    const int cls0 = g_tcs[cb], cls1 = g_tcs[cb + 1];
                    if (cls0 >= 0 && cls0 != lb)
                        lsum += fmaxf(acc[mi][ni][half * 2 + 0] + base, 0.f);
                    if (cls1 >= 0 && cls1 != lb)
                        lsum += fmaxf(acc[mi][ni][half * 2 + 1] + base, 0.f);
                    acc[mi][ni][half * 2 + 0] = 0.f;
                    acc[mi][ni][half * 2 + 1] = 0.f;
                }
            }
        }
        // warp-shuffle reduce, then cross-warp via smem
        #pragma unroll
        for (int o = 16; o > 0; o >>= 1) lsum += __shfl_down_sync(0xffffffffu, lsum, o);
        float* red = (float*)(smem + RED_OFF);
        if (lane == 0) red[wid] = lsum;
        __syncthreads();
        if (tid < 16) {
            float v = red[tid];
            #pragma unroll
            for (int o = 8; o > 0; o >>= 1) v += __shfl_down_sync(0xffffu, v, o);
            if (tid == 0) g_partial[tile] = v;
        }
        __syncthreads();
    }
}

// ---------------- deterministic final reduce ----------------
__global__ void final_reduce_kernel(float* __restrict__ out, int n) {
    __shared__ float red[256];
    int tid = threadIdx.x;
    float s = 0.f;
    for (int i = tid; i < n; i += 256) s += g_partial[i];
    red[tid] = s;
    __syncthreads();
    #pragma unroll
    for (int o = 128; o > 0; o >>= 1) {
        if (tid < o) red[tid] += red[tid + o];
        __syncthreads();
    }
    if (tid == 0) out[0] = red[0];
}

extern "C" void kernel_launch(void* const* d_in, const int* in_sizes, int n_in,
                              void* d_out, int out_size) {
    const float* pred   = (const float*)d_in[0];
    const int*   label  = (const int*)d_in[1];
    const int*   tclass = (const int*)d_in[2];
    const float* sig    = (const float*)d_in[3];
    float* out = (float*)d_out;

    const int B = in_sizes[1];
    const int C = in_sizes[2];

    {
        dim3 tg((C + 31) / 32, DDIM / 32);
        transpose_sig_kernel<<<tg, 256>>>(sig, C);
    }
    prep_sig_kernel<<<(CPAD * 32) / 256, 256>>>(tclass, C);
    {
        int n8 = B * DDIM / 8;
        prep_pred_kernel<<<(n8 + 255) / 256, 256>>>(pred, n8);
    }
    gt_kernel<<<(B + 7) / 8, 256>>>(pred, label, B);

    const int nt = (CPAD / 256) * (B / 128);
    cudaFuncSetAttribute(hinge_mma_kernel, cudaFuncAttributeMaxDynamicSharedMemorySize, SMEM_TOTAL);
    hinge_mma_kernel<<<PGRID, 512, SMEM_TOTAL>>>(label, nt);

    final_reduce_kernel<<<1, 256>>>(out, nt);
}